// round 11
// baseline (speedup 1.0000x reference)
#include <cuda_runtime.h>
#include <cuda_bf16.h>
#include <math.h>

// Problem constants (fixed by the dataset)
#define BMAX 1024
#define EMAX 32768
#define CC   64
#define DD   64

// Scratch (static device globals — no allocation allowed)
__device__ long long g_offsets[BMAX + 1];
__device__ int       g_edge_user[EMAX];
__device__ float     g_M2t[DD * DD];     // [j][d] : friend part of Wb^T Wf
__device__ float     g_vself[BMAX * DD];
__device__ float     g_v[(size_t)EMAX * DD];

// ---------------------------------------------------------------------------
// Combo kernel (1024 threads/block, grid = 69):
//   block 0      : dtype-robust scan of counts -> offsets + edge->user map
//   blocks 1..4  : M2t[j][d] = sum_f Wb[f][d] * Wf[f][64+j]
//   blocks 5..68 : vself[u] = Wb^T (Wf[:, :64] @ self_x[u])   (16 users/block)
// All three parts are independent (vself no longer needs a materialized M1).
// ---------------------------------------------------------------------------
__global__ __launch_bounds__(1024)
void combo_kernel(const void* __restrict__ counts_raw, int B, int E,
                  const float* __restrict__ Wf, const float* __restrict__ Wb,
                  const float* __restrict__ self_x) {
    int b = blockIdx.x;
    int t = threadIdx.x;

    if (b == 0) {
        // ---- setup: scan + edge_user fill ----
        __shared__ long long s[BMAX];
        __shared__ int use64;
        const long long* c64 = (const long long*)counts_raw;
        const int*       c32 = (const int*)counts_raw;

        long long v64 = (t < B) ? c64[t] : 0;
        s[t] = v64;
        __syncthreads();
        for (int o = BMAX >> 1; o > 0; o >>= 1) {
            if (t < o) s[t] += s[t + o];
            __syncthreads();
        }
        if (t == 0) use64 = (s[0] == (long long)E) ? 1 : 0;
        __syncthreads();
        int u64 = use64;
        __syncthreads();

        long long c = 0;
        if (t < B) c = u64 ? c64[t] : (long long)c32[t];
        if (c < 0) c = 0;
        if (c > (long long)EMAX) c = EMAX;

        s[t] = c;
        __syncthreads();
        for (int o = 1; o < BMAX; o <<= 1) {
            long long add = (t >= o) ? s[t - o] : 0;
            __syncthreads();
            s[t] += add;
            __syncthreads();
        }
        if (t == 0) g_offsets[0] = 0;
        if (t < B) g_offsets[t + 1] = s[t];
        long long off = s[t] - c;
        if (t < B) {
            for (long long i = 0; i < c; i++) {
                long long idx = off + i;
                if (idx >= 0 && idx < (long long)EMAX) g_edge_user[idx] = t;
            }
        }
    } else if (b <= 4) {
        // ---- M2t ----
        int idx = (b - 1) * 1024 + t;          // 0..4095
        int d = idx & 63;
        int j = (idx >> 6) & 63;
        float acc = 0.f;
#pragma unroll 8
        for (int f = 0; f < 64; f++)
            acc = fmaf(Wb[f * 64 + d], Wf[f * 128 + 64 + j], acc);
        g_M2t[j * 64 + d] = acc;
    } else {
        // ---- vself direct: 16 users per block ----
        __shared__ float sx[16][64];
        __shared__ float p[16][64];
        int sub = t >> 6;          // 0..15
        int l = t & 63;            // 0..63
        int u = (b - 5) * 16 + sub;
        sx[sub][l] = self_x[u * 64 + l];
        __syncthreads();
        // p[f] = Wf[f, :64] . sx
        {
            float acc = 0.f;
#pragma unroll 8
            for (int j = 0; j < 64; j++)
                acc = fmaf(Wf[l * 128 + j], sx[sub][j], acc);
            p[sub][l] = acc;
        }
        __syncthreads();
        // vself[d] = sum_f Wb[f][d] * p[f]
        {
            float acc = 0.f;
#pragma unroll 8
            for (int f = 0; f < 64; f++)
                acc = fmaf(Wb[f * 64 + l], p[sub][f], acc);
            g_vself[u * 64 + l] = acc;
        }
    }
}

// ---------------------------------------------------------------------------
// vedge (v4): v[e][d] = vself[u(e)][d] + sum_j M2t[j][d] * friend_x[e][j]
// 4 edges per thread (16 FMA per 32B of LDS), 64 edges/block, grid = 512.
// ---------------------------------------------------------------------------
#define FXPAD 68
__global__ __launch_bounds__(256) void vedge_kernel(const float* __restrict__ fx_g) {
    __shared__ float4 M2sh[64 * 16];          // [j][q], 16 KB
    __shared__ float  fxs[64 * FXPAD];        // 64 edges, padded rows (17.4 KB)
    int t = threadIdx.x;

    const float4* M2g = (const float4*)g_M2t;
    for (int i = t; i < 1024; i += 256) M2sh[i] = M2g[i];

    int e0 = blockIdx.x * 64;
    for (int i = t; i < 1024; i += 256) {
        int ee = i >> 4, qq = i & 15;
        float4 f = ((const float4*)(fx_g + (size_t)(e0 + ee) * 64))[qq];
        *((float4*)(fxs + ee * FXPAD + qq * 4)) = f;
    }
    __syncthreads();

    int q = t & 15;      // d-chunk
    int r = t >> 4;      // 0..15, edges 4r..4r+3
    int ebase = e0 + 4 * r;

    float4 acc[4];
#pragma unroll
    for (int k = 0; k < 4; k++) {
        int u = g_edge_user[ebase + k];
        acc[k] = ((const float4*)(g_vself + (size_t)u * 64))[q];
    }
    const float* f0 = fxs + (4 * r + 0) * FXPAD;
    const float* f1 = fxs + (4 * r + 1) * FXPAD;
    const float* f2 = fxs + (4 * r + 2) * FXPAD;
    const float* f3 = fxs + (4 * r + 3) * FXPAD;
#pragma unroll 8
    for (int j = 0; j < 64; j++) {
        float4 m = M2sh[j * 16 + q];
        float a = f0[j], bq = f1[j], cq = f2[j], dq = f3[j];
        acc[0].x = fmaf(m.x, a, acc[0].x);  acc[0].y = fmaf(m.y, a, acc[0].y);
        acc[0].z = fmaf(m.z, a, acc[0].z);  acc[0].w = fmaf(m.w, a, acc[0].w);
        acc[1].x = fmaf(m.x, bq, acc[1].x); acc[1].y = fmaf(m.y, bq, acc[1].y);
        acc[1].z = fmaf(m.z, bq, acc[1].z); acc[1].w = fmaf(m.w, bq, acc[1].w);
        acc[2].x = fmaf(m.x, cq, acc[2].x); acc[2].y = fmaf(m.y, cq, acc[2].y);
        acc[2].z = fmaf(m.z, cq, acc[2].z); acc[2].w = fmaf(m.w, cq, acc[2].w);
        acc[3].x = fmaf(m.x, dq, acc[3].x); acc[3].y = fmaf(m.y, dq, acc[3].y);
        acc[3].z = fmaf(m.z, dq, acc[3].z); acc[3].w = fmaf(m.w, dq, acc[3].w);
    }
#pragma unroll
    for (int k = 0; k < 4; k++)
        ((float4*)(g_v + (size_t)(ebase + k) * 64))[q] = acc[k];
}

// ---------------------------------------------------------------------------
// Main (v4): coalesced warp-per-edge + ballot-preloaded masks.
// Lane l: h=l&15 (16B chunk), side=l>>4 (row parity). Each LDG.128 covers
// 512B contiguous (4 wavefronts, minimum). Masks preloaded via 2 coalesced
// loads + ballot -> register bitmap -> tile loads are register-predicated,
// fully batchable (high MLP). Temporal exp precomputed per lane, shfl'd.
// ---------------------------------------------------------------------------
__global__ __launch_bounds__(256)
void main_kernel(const float* __restrict__ common_x,
                 const float* __restrict__ common_time,
                 const int*   __restrict__ common_src_mask,
                 float* __restrict__ out, int max_n, long long out_elems) {
    int warp = threadIdx.x >> 5;   // 0..7
    int lane = threadIdx.x & 31;
    int e = blockIdx.x * 8 + warp;
    int h = lane & 15;
    int side = lane >> 4;

    const int*   mrow = common_src_mask + (size_t)e * 64;
    const float* trow = common_time + (size_t)e * 64;

    int mk0 = mrow[lane];
    int mk1 = mrow[lane + 32];
    float ex0 = __expf(fmaf(trow[lane],      -1e-6f, 1.0f));
    float ex1 = __expf(fmaf(trow[lane + 32], -1e-6f, 1.0f));
    unsigned bm0 = __ballot_sync(0xffffffffu, mk0 != 0);  // bit l = mask[l]
    unsigned bm1 = __ballot_sync(0xffffffffu, mk1 != 0);  // bit l = mask[l+32]

    float4 v4 = *(const float4*)(g_v + (size_t)e * 64 + h * 4);
    const float* base = common_x + (size_t)e * 64 * 64;

    float wacc = 0.f;
#pragma unroll
    for (int g = 0; g < 32; g++) {
        int sh = ((2 * g) & 31) + side;            // row & 31
        unsigned bits = (g < 16) ? bm0 : bm1;
        bool mk = (bits >> sh) & 1u;
        int row = 2 * g + side;

        float partial = 0.f;
        if (mk) {
            float4 x = *(const float4*)(base + row * 64 + h * 4);
            partial = fmaf(x.x, v4.x, fmaf(x.y, v4.y,
                      fmaf(x.z, v4.z, x.w * v4.w)));
        }
        partial += __shfl_xor_sync(0xffffffffu, partial, 8);
        partial += __shfl_xor_sync(0xffffffffu, partial, 4);
        partial += __shfl_xor_sync(0xffffffffu, partial, 2);
        partial += __shfl_xor_sync(0xffffffffu, partial, 1);
        // temporal factor for 'row' lives at lane sh
        float exv = __shfl_sync(0xffffffffu, (g < 16) ? ex0 : ex1, sh);
        if (mk) {
            float sp = fmaxf(partial, 0.f)
                     + __logf(1.0f + __expf(-fabsf(partial)));
            wacc = fmaf(sp, exv, wacc);
        }
    }
    // every lane of a half holds that half's sum (xor reduce is symmetric);
    // but wacc accumulated identically across the 16 lanes of each half.
    wacc += __shfl_xor_sync(0xffffffffu, wacc, 16);
    if (lane == 0) {
        int u = g_edge_user[e];
        long long oi = (long long)u * max_n + (long long)(e - g_offsets[u]);
        if (oi >= 0 && oi < out_elems)
            out[oi] = wacc;
    }
}

// ---------------------------------------------------------------------------
extern "C" void kernel_launch(void* const* d_in, const int* in_sizes, int n_in,
                              void* d_out, int out_size) {
    const float* self_x      = (const float*)d_in[0];
    const float* common_x    = (const float*)d_in[1];
    const float* common_time = (const float*)d_in[2];
    const int*   src_mask    = (const int*)d_in[3];
    const float* friend_x    = (const float*)d_in[4];
    const void*  counts      = (const void*)d_in[5];
    const float* W_friend    = (const float*)d_in[6];
    const float* W_beta      = (const float*)d_in[7];
    float*       out         = (float*)d_out;

    int B = in_sizes[5];
    int E = in_sizes[4] / 64;
    int max_n = out_size / B;

    combo_kernel<<<69, 1024>>>(counts, B, E, W_friend, W_beta, self_x);
    vedge_kernel<<<E / 64, 256>>>(friend_x);
    cudaMemsetAsync(d_out, 0, (size_t)out_size * sizeof(float), 0);
    main_kernel<<<E / 8, 256>>>(common_x, common_time, src_mask, out, max_n,
                                (long long)out_size);
}

// round 12
// speedup vs baseline: 1.1195x; 1.1195x over previous
#include <cuda_runtime.h>
#include <cuda_bf16.h>
#include <math.h>

// Problem constants (fixed by the dataset)
#define BMAX 1024
#define EMAX 32768
#define CC   64
#define DD   64

// Scratch (static device globals — no allocation allowed)
__device__ long long g_offsets[BMAX + 1];
__device__ int       g_edge_user[EMAX];
__device__ float     g_M2t[DD * DD];     // [j][d] : friend part of Wb^T Wf
__device__ float     g_vself[BMAX * DD];
__device__ float     g_v[(size_t)EMAX * DD];

// ---------------------------------------------------------------------------
// Combo kernel (1024 threads/block, grid = 69):
//   block 0      : dtype-robust scan of counts -> offsets + edge->user map
//   blocks 1..4  : M2t[j][d] = sum_f Wb[f][d] * Wf[f][64+j]   (coalesced)
//   blocks 5..68 : vself[u] = Wb^T (Wf[:, :64] @ self_x[u])   (16 users/block)
//                  Weights staged in SMEM coalesced; LDS phases conflict-free.
// ---------------------------------------------------------------------------
struct VsSmem {
    float Wfh[64][65];   // Wf[:, :64], padded (l*65+j -> conflict-free)
    float Wbsh[64][64];  // Wb, [f][d]  (lane-consecutive d -> conflict-free)
    float sx[16][64];
    float p[16][64];
};
union ComboSmem {
    long long s[BMAX];
    VsSmem vs;
};

__global__ __launch_bounds__(1024)
void combo_kernel(const void* __restrict__ counts_raw, int B, int E,
                  const float* __restrict__ Wf, const float* __restrict__ Wb,
                  const float* __restrict__ self_x) {
    __shared__ ComboSmem sm;
    int b = blockIdx.x;
    int t = threadIdx.x;

    if (b == 0) {
        // ---- setup: scan + edge_user fill ----
        __shared__ int use64;
        long long* s = sm.s;
        const long long* c64 = (const long long*)counts_raw;
        const int*       c32 = (const int*)counts_raw;

        long long v64 = (t < B) ? c64[t] : 0;
        s[t] = v64;
        __syncthreads();
        for (int o = BMAX >> 1; o > 0; o >>= 1) {
            if (t < o) s[t] += s[t + o];
            __syncthreads();
        }
        if (t == 0) use64 = (s[0] == (long long)E) ? 1 : 0;
        __syncthreads();
        int u64 = use64;
        __syncthreads();

        long long c = 0;
        if (t < B) c = u64 ? c64[t] : (long long)c32[t];
        if (c < 0) c = 0;
        if (c > (long long)EMAX) c = EMAX;

        s[t] = c;
        __syncthreads();
        for (int o = 1; o < BMAX; o <<= 1) {
            long long add = (t >= o) ? s[t - o] : 0;
            __syncthreads();
            s[t] += add;
            __syncthreads();
        }
        if (t == 0) g_offsets[0] = 0;
        if (t < B) g_offsets[t + 1] = s[t];
        long long off = s[t] - c;
        if (t < B) {
            for (long long i = 0; i < c; i++) {
                long long idx = off + i;
                if (idx >= 0 && idx < (long long)EMAX) g_edge_user[idx] = t;
            }
        }
    } else if (b <= 4) {
        // ---- M2t (coalesced: d and j are lane-consecutive) ----
        int idx = (b - 1) * 1024 + t;          // 0..4095
        int d = idx & 63;
        int j = (idx >> 6) & 63;
        float acc = 0.f;
#pragma unroll 8
        for (int f = 0; f < 64; f++)
            acc = fmaf(Wb[f * 64 + d], Wf[f * 128 + 64 + j], acc);
        g_M2t[j * 64 + d] = acc;
    } else {
        // ---- vself: 16 users/block, weights staged in SMEM coalesced ----
        VsSmem& S = sm.vs;
        // Wf[:, :64]: per row f, 64 consecutive floats (coalesced)
        for (int i = t; i < 4096; i += 1024) {
            int f = i >> 6, j = i & 63;
            S.Wfh[f][j] = Wf[f * 128 + j];
        }
        // Wb: fully contiguous
        for (int i = t; i < 4096; i += 1024) {
            S.Wbsh[i >> 6][i & 63] = Wb[i];
        }
        int sub = t >> 6;          // 0..15 (user within block)
        int l = t & 63;            // 0..63
        int u = (b - 5) * 16 + sub;
        S.sx[sub][l] = self_x[u * 64 + l];
        __syncthreads();

        // p[sub][l] = Wf[l, :64] . sx[sub]
        {
            float acc = 0.f;
#pragma unroll 16
            for (int j = 0; j < 64; j++)
                acc = fmaf(S.Wfh[l][j], S.sx[sub][j], acc);
            S.p[sub][l] = acc;
        }
        __syncthreads();
        // vself[u][l] = sum_f Wb[f][l] * p[sub][f]
        {
            float acc = 0.f;
#pragma unroll 16
            for (int f = 0; f < 64; f++)
                acc = fmaf(S.Wbsh[f][l], S.p[sub][f], acc);
            g_vself[u * 64 + l] = acc;
        }
    }
}

// ---------------------------------------------------------------------------
// vedge (v4): v[e][d] = vself[u(e)][d] + sum_j M2t[j][d] * friend_x[e][j]
// 4 edges per thread (16 FMA per 32B of LDS), 64 edges/block, grid = 512.
// ---------------------------------------------------------------------------
#define FXPAD 68
__global__ __launch_bounds__(256) void vedge_kernel(const float* __restrict__ fx_g) {
    __shared__ float4 M2sh[64 * 16];          // [j][q], 16 KB
    __shared__ float  fxs[64 * FXPAD];        // 64 edges, padded rows (17.4 KB)
    int t = threadIdx.x;

    const float4* M2g = (const float4*)g_M2t;
    for (int i = t; i < 1024; i += 256) M2sh[i] = M2g[i];

    int e0 = blockIdx.x * 64;
    for (int i = t; i < 1024; i += 256) {
        int ee = i >> 4, qq = i & 15;
        float4 f = ((const float4*)(fx_g + (size_t)(e0 + ee) * 64))[qq];
        *((float4*)(fxs + ee * FXPAD + qq * 4)) = f;
    }
    __syncthreads();

    int q = t & 15;      // d-chunk
    int r = t >> 4;      // 0..15, edges 4r..4r+3
    int ebase = e0 + 4 * r;

    float4 acc[4];
#pragma unroll
    for (int k = 0; k < 4; k++) {
        int u = g_edge_user[ebase + k];
        acc[k] = ((const float4*)(g_vself + (size_t)u * 64))[q];
    }
    const float* f0 = fxs + (4 * r + 0) * FXPAD;
    const float* f1 = fxs + (4 * r + 1) * FXPAD;
    const float* f2 = fxs + (4 * r + 2) * FXPAD;
    const float* f3 = fxs + (4 * r + 3) * FXPAD;
#pragma unroll 8
    for (int j = 0; j < 64; j++) {
        float4 m = M2sh[j * 16 + q];
        float a = f0[j], bq = f1[j], cq = f2[j], dq = f3[j];
        acc[0].x = fmaf(m.x, a, acc[0].x);  acc[0].y = fmaf(m.y, a, acc[0].y);
        acc[0].z = fmaf(m.z, a, acc[0].z);  acc[0].w = fmaf(m.w, a, acc[0].w);
        acc[1].x = fmaf(m.x, bq, acc[1].x); acc[1].y = fmaf(m.y, bq, acc[1].y);
        acc[1].z = fmaf(m.z, bq, acc[1].z); acc[1].w = fmaf(m.w, bq, acc[1].w);
        acc[2].x = fmaf(m.x, cq, acc[2].x); acc[2].y = fmaf(m.y, cq, acc[2].y);
        acc[2].z = fmaf(m.z, cq, acc[2].z); acc[2].w = fmaf(m.w, cq, acc[2].w);
        acc[3].x = fmaf(m.x, dq, acc[3].x); acc[3].y = fmaf(m.y, dq, acc[3].y);
        acc[3].z = fmaf(m.z, dq, acc[3].z); acc[3].w = fmaf(m.w, dq, acc[3].w);
    }
#pragma unroll
    for (int k = 0; k < 4; k++)
        ((float4*)(g_v + (size_t)(ebase + k) * 64))[q] = acc[k];
}

// ---------------------------------------------------------------------------
// Main: coalesced warp-per-edge + ballot-preloaded masks (register-predicated
// LDG.128, full MLP). Temporal exp precomputed per lane, fetched via shfl.
// ---------------------------------------------------------------------------
__global__ __launch_bounds__(256)
void main_kernel(const float* __restrict__ common_x,
                 const float* __restrict__ common_time,
                 const int*   __restrict__ common_src_mask,
                 float* __restrict__ out, int max_n, long long out_elems) {
    int warp = threadIdx.x >> 5;   // 0..7
    int lane = threadIdx.x & 31;
    int e = blockIdx.x * 8 + warp;
    int h = lane & 15;
    int side = lane >> 4;

    const int*   mrow = common_src_mask + (size_t)e * 64;
    const float* trow = common_time + (size_t)e * 64;

    int mk0 = mrow[lane];
    int mk1 = mrow[lane + 32];
    float ex0 = __expf(fmaf(trow[lane],      -1e-6f, 1.0f));
    float ex1 = __expf(fmaf(trow[lane + 32], -1e-6f, 1.0f));
    unsigned bm0 = __ballot_sync(0xffffffffu, mk0 != 0);
    unsigned bm1 = __ballot_sync(0xffffffffu, mk1 != 0);

    float4 v4 = *(const float4*)(g_v + (size_t)e * 64 + h * 4);
    const float* base = common_x + (size_t)e * 64 * 64;

    float wacc = 0.f;
#pragma unroll
    for (int g = 0; g < 32; g++) {
        int sh = ((2 * g) & 31) + side;            // row & 31
        unsigned bits = (g < 16) ? bm0 : bm1;
        bool mk = (bits >> sh) & 1u;
        int row = 2 * g + side;

        float partial = 0.f;
        if (mk) {
            float4 x = *(const float4*)(base + row * 64 + h * 4);
            partial = fmaf(x.x, v4.x, fmaf(x.y, v4.y,
                      fmaf(x.z, v4.z, x.w * v4.w)));
        }
        partial += __shfl_xor_sync(0xffffffffu, partial, 8);
        partial += __shfl_xor_sync(0xffffffffu, partial, 4);
        partial += __shfl_xor_sync(0xffffffffu, partial, 2);
        partial += __shfl_xor_sync(0xffffffffu, partial, 1);
        float exv = __shfl_sync(0xffffffffu, (g < 16) ? ex0 : ex1, sh);
        if (mk) {
            float sp = fmaxf(partial, 0.f)
                     + __logf(1.0f + __expf(-fabsf(partial)));
            wacc = fmaf(sp, exv, wacc);
        }
    }
    wacc += __shfl_xor_sync(0xffffffffu, wacc, 16);
    if (lane == 0) {
        int u = g_edge_user[e];
        long long oi = (long long)u * max_n + (long long)(e - g_offsets[u]);
        if (oi >= 0 && oi < out_elems)
            out[oi] = wacc;
    }
}

// ---------------------------------------------------------------------------
extern "C" void kernel_launch(void* const* d_in, const int* in_sizes, int n_in,
                              void* d_out, int out_size) {
    const float* self_x      = (const float*)d_in[0];
    const float* common_x    = (const float*)d_in[1];
    const float* common_time = (const float*)d_in[2];
    const int*   src_mask    = (const int*)d_in[3];
    const float* friend_x    = (const float*)d_in[4];
    const void*  counts      = (const void*)d_in[5];
    const float* W_friend    = (const float*)d_in[6];
    const float* W_beta      = (const float*)d_in[7];
    float*       out         = (float*)d_out;

    int B = in_sizes[5];
    int E = in_sizes[4] / 64;
    int max_n = out_size / B;

    combo_kernel<<<69, 1024>>>(counts, B, E, W_friend, W_beta, self_x);
    vedge_kernel<<<E / 64, 256>>>(friend_x);
    cudaMemsetAsync(d_out, 0, (size_t)out_size * sizeof(float), 0);
    main_kernel<<<E / 8, 256>>>(common_x, common_time, src_mask, out, max_n,
                                (long long)out_size);
}

// round 13
// speedup vs baseline: 1.6584x; 1.4814x over previous
#include <cuda_runtime.h>
#include <cuda_bf16.h>
#include <math.h>

// Problem constants (fixed by the dataset)
#define BMAX 1024
#define EMAX 32768

// Scratch (static device globals — no allocation allowed)
__device__ long long g_offsets[BMAX + 1];
__device__ int       g_edge_user[EMAX];
__device__ float     g_M2t[64 * 64];      // [j][d] : friend part of Wb^T Wf
__device__ float     g_vself[BMAX * 64];

// ---------------------------------------------------------------------------
// Combo kernel (1024 threads/block, grid = 69):
//   block 0      : dtype-robust scan of counts -> offsets + edge->user map
//   blocks 1..4  : M2t[j][d] = sum_f Wb[f][d] * Wf[f][64+j]   (coalesced)
//   blocks 5..68 : vself[u] = Wb^T (Wf[:, :64] @ self_x[u])   (16 users/block)
//                  float4 LDS both phases; Wb staged transposed for phase 2.
// ---------------------------------------------------------------------------
struct VsSmem {
    float Wfh[64][68];   // Wf[:, :64], rows padded to 68 (272B, 16B-aligned)
    float Wbt[64][68];   // Wb transposed [d][f], padded
    float sx[16][64];
    float p[16][64];
};
union ComboSmem {
    long long s[BMAX];
    VsSmem vs;
};

__global__ __launch_bounds__(1024)
void combo_kernel(const void* __restrict__ counts_raw, int B, int E,
                  const float* __restrict__ Wf, const float* __restrict__ Wb,
                  const float* __restrict__ self_x) {
    __shared__ ComboSmem sm;
    int b = blockIdx.x;
    int t = threadIdx.x;

    if (b == 0) {
        // ---- setup: scan + edge_user fill ----
        __shared__ int use64;
        long long* s = sm.s;
        const long long* c64 = (const long long*)counts_raw;
        const int*       c32 = (const int*)counts_raw;

        long long v64 = (t < B) ? c64[t] : 0;
        s[t] = v64;
        __syncthreads();
        for (int o = BMAX >> 1; o > 0; o >>= 1) {
            if (t < o) s[t] += s[t + o];
            __syncthreads();
        }
        if (t == 0) use64 = (s[0] == (long long)E) ? 1 : 0;
        __syncthreads();
        int u64 = use64;
        __syncthreads();

        long long c = 0;
        if (t < B) c = u64 ? c64[t] : (long long)c32[t];
        if (c < 0) c = 0;
        if (c > (long long)EMAX) c = EMAX;

        s[t] = c;
        __syncthreads();
        for (int o = 1; o < BMAX; o <<= 1) {
            long long add = (t >= o) ? s[t - o] : 0;
            __syncthreads();
            s[t] += add;
            __syncthreads();
        }
        if (t == 0) g_offsets[0] = 0;
        if (t < B) g_offsets[t + 1] = s[t];
        long long off = s[t] - c;
        if (t < B) {
            for (long long i = 0; i < c; i++) {
                long long idx = off + i;
                if (idx >= 0 && idx < (long long)EMAX) g_edge_user[idx] = t;
            }
        }
    } else if (b <= 4) {
        // ---- M2t (coalesced: d and j lane-consecutive) ----
        int idx = (b - 1) * 1024 + t;          // 0..4095
        int d = idx & 63;
        int j = (idx >> 6) & 63;
        float acc = 0.f;
#pragma unroll 8
        for (int f = 0; f < 64; f++)
            acc = fmaf(Wb[f * 64 + d], Wf[f * 128 + 64 + j], acc);
        g_M2t[j * 64 + d] = acc;
    } else {
        // ---- vself: 16 users/block, float4 LDS phases ----
        VsSmem& S = sm.vs;
        for (int i = t; i < 4096; i += 1024) {
            int f = i >> 6, j = i & 63;
            S.Wfh[f][j] = Wf[f * 128 + j];     // coalesced read
        }
        for (int i = t; i < 4096; i += 1024) {
            int f = i >> 6, d = i & 63;
            S.Wbt[d][f] = Wb[i];               // coalesced read, transp. store
        }
        int sub = t >> 6;          // 0..15 (user within block)
        int l = t & 63;            // 0..63
        int u = (b - 5) * 16 + sub;
        S.sx[sub][l] = self_x[u * 64 + l];
        __syncthreads();

        // phase 1: p[sub][l] = Wf[l, :64] . sx[sub]   (float4 LDS)
        {
            const float4* wr = (const float4*)&S.Wfh[l][0];
            const float4* xr = (const float4*)&S.sx[sub][0];
            float acc = 0.f;
#pragma unroll
            for (int jb = 0; jb < 16; jb++) {
                float4 wv = wr[jb], xv = xr[jb];
                acc = fmaf(wv.x, xv.x, fmaf(wv.y, xv.y,
                      fmaf(wv.z, xv.z, fmaf(wv.w, xv.w, acc))));
            }
            S.p[sub][l] = acc;
        }
        __syncthreads();
        // phase 2: vself[u][l] = sum_f Wbt[l][f] * p[sub][f]   (float4 LDS)
        {
            const float4* wr = (const float4*)&S.Wbt[l][0];
            const float4* pr = (const float4*)&S.p[sub][0];
            float acc = 0.f;
#pragma unroll
            for (int fb = 0; fb < 16; fb++) {
                float4 wv = wr[fb], pv = pr[fb];
                acc = fmaf(wv.x, pv.x, fmaf(wv.y, pv.y,
                      fmaf(wv.z, pv.z, fmaf(wv.w, pv.w, acc))));
            }
            g_vself[u * 64 + l] = acc;
        }
    }
}

// ---------------------------------------------------------------------------
// Main (v5): fused v-compute + compacted masked streaming.
// 8 edges/block (1 per warp).
//  Phase A: stage M2 (16KB) block-wide; each warp computes its edge's
//           v[64] = vself[u] + M2^T fx[e] into shared (warp-local sync only).
//  Phase B: ballot-compact active rows into a list; loop ONLY over active
//           rows (~32 of 64): unpredicated coalesced LDG.128, 4-shfl reduce,
//           softplus * exsh[row]. All per-iter costs halve vs full loop.
// ---------------------------------------------------------------------------
__global__ __launch_bounds__(256)
void main_kernel(const float* __restrict__ common_x,
                 const float* __restrict__ common_time,
                 const int*   __restrict__ common_src_mask,
                 const float* __restrict__ friend_x,
                 float* __restrict__ out, int max_n, long long out_elems) {
    __shared__ float M2sh[64 * 64];   // [j][d], 16 KB
    __shared__ float fxsh[8][64];
    __shared__ float vsh[8][64];
    __shared__ float exsh[8][64];
    __shared__ int   lst[8][64];

    int tid = threadIdx.x;
    int w = tid >> 5, lane = tid & 31;
    int e = blockIdx.x * 8 + w;

    // stage M2 cooperatively
    {
        const float4* src = (const float4*)g_M2t;
        float4* dst = (float4*)M2sh;
        for (int i = tid; i < 1024; i += 256) dst[i] = src[i];
    }
    // stage this warp's fx
    fxsh[w][lane]      = friend_x[(size_t)e * 64 + lane];
    fxsh[w][lane + 32] = friend_x[(size_t)e * 64 + lane + 32];
    int u = g_edge_user[e];
    __syncthreads();

    // ---- Phase A: v for this edge; lane owns d = 2*lane, 2*lane+1 ----
    {
        float2 acc = *(const float2*)(g_vself + (size_t)u * 64 + 2 * lane);
#pragma unroll 8
        for (int j = 0; j < 64; j++) {
            float2 m = *(const float2*)(M2sh + j * 64 + 2 * lane);
            float f = fxsh[w][j];
            acc.x = fmaf(m.x, f, acc.x);
            acc.y = fmaf(m.y, f, acc.y);
        }
        *(float2*)(&vsh[w][2 * lane]) = acc;
    }

    // ---- masks / temporal / compaction ----
    const int*   mrow = common_src_mask + (size_t)e * 64;
    const float* trow = common_time + (size_t)e * 64;
    int mk0 = mrow[lane];
    int mk1 = mrow[lane + 32];
    exsh[w][lane]      = __expf(fmaf(trow[lane],      -1e-6f, 1.0f));
    exsh[w][lane + 32] = __expf(fmaf(trow[lane + 32], -1e-6f, 1.0f));
    unsigned bm0 = __ballot_sync(0xffffffffu, mk0 != 0);
    unsigned bm1 = __ballot_sync(0xffffffffu, mk1 != 0);
    int n0 = __popc(bm0);
    if (mk0) lst[w][__popc(bm0 & ((1u << lane) - 1u))] = lane;
    if (mk1) lst[w][n0 + __popc(bm1 & ((1u << lane) - 1u))] = lane + 32;
    int n_act = n0 + __popc(bm1);
    __syncwarp();

    int h = lane & 15, side = lane >> 4;
    float4 v4 = *(const float4*)(&vsh[w][h * 4]);
    const float* base = common_x + (size_t)e * 4096;

    float wacc = 0.f;
    int kmax = (n_act + 1) >> 1;          // pairs of rows per step

    // 2x unrolled over pair-steps for MLP
    int g = 0;
    for (; g + 2 <= kmax; g += 2) {
        int iA = 2 * g + side;
        int iB = 2 * (g + 1) + side;
        bool vA = iA < n_act, vB = iB < n_act;
        int rA = lst[w][vA ? iA : 0];
        int rB = lst[w][vB ? iB : 0];
        float pA = 0.f, pB = 0.f;
        if (vA) {
            float4 x = *(const float4*)(base + rA * 64 + h * 4);
            pA = fmaf(x.x, v4.x, fmaf(x.y, v4.y, fmaf(x.z, v4.z, x.w * v4.w)));
        }
        if (vB) {
            float4 x = *(const float4*)(base + rB * 64 + h * 4);
            pB = fmaf(x.x, v4.x, fmaf(x.y, v4.y, fmaf(x.z, v4.z, x.w * v4.w)));
        }
#pragma unroll
        for (int o = 8; o > 0; o >>= 1) {
            pA += __shfl_xor_sync(0xffffffffu, pA, o);
            pB += __shfl_xor_sync(0xffffffffu, pB, o);
        }
        if (vA) {
            float sp = fmaxf(pA, 0.f) + __logf(1.0f + __expf(-fabsf(pA)));
            wacc = fmaf(sp, exsh[w][rA], wacc);
        }
        if (vB) {
            float sp = fmaxf(pB, 0.f) + __logf(1.0f + __expf(-fabsf(pB)));
            wacc = fmaf(sp, exsh[w][rB], wacc);
        }
    }
    for (; g < kmax; g++) {
        int iA = 2 * g + side;
        bool vA = iA < n_act;
        int rA = lst[w][vA ? iA : 0];
        float pA = 0.f;
        if (vA) {
            float4 x = *(const float4*)(base + rA * 64 + h * 4);
            pA = fmaf(x.x, v4.x, fmaf(x.y, v4.y, fmaf(x.z, v4.z, x.w * v4.w)));
        }
#pragma unroll
        for (int o = 8; o > 0; o >>= 1)
            pA += __shfl_xor_sync(0xffffffffu, pA, o);
        if (vA) {
            float sp = fmaxf(pA, 0.f) + __logf(1.0f + __expf(-fabsf(pA)));
            wacc = fmaf(sp, exsh[w][rA], wacc);
        }
    }

    wacc += __shfl_xor_sync(0xffffffffu, wacc, 16);
    if (lane == 0) {
        long long oi = (long long)u * max_n + (long long)(e - g_offsets[u]);
        if (oi >= 0 && oi < out_elems)
            out[oi] = wacc;
    }
}

// ---------------------------------------------------------------------------
extern "C" void kernel_launch(void* const* d_in, const int* in_sizes, int n_in,
                              void* d_out, int out_size) {
    const float* self_x      = (const float*)d_in[0];
    const float* common_x    = (const float*)d_in[1];
    const float* common_time = (const float*)d_in[2];
    const int*   src_mask    = (const int*)d_in[3];
    const float* friend_x    = (const float*)d_in[4];
    const void*  counts      = (const void*)d_in[5];
    const float* W_friend    = (const float*)d_in[6];
    const float* W_beta      = (const float*)d_in[7];
    float*       out         = (float*)d_out;

    int B = in_sizes[5];
    int E = in_sizes[4] / 64;
    int max_n = out_size / B;

    combo_kernel<<<69, 1024>>>(counts, B, E, W_friend, W_beta, self_x);
    cudaMemsetAsync(d_out, 0, (size_t)out_size * sizeof(float), 0);
    main_kernel<<<E / 8, 256>>>(common_x, common_time, src_mask, friend_x,
                                out, max_n, (long long)out_size);
}

// round 14
// speedup vs baseline: 1.6841x; 1.0155x over previous
#include <cuda_runtime.h>
#include <cuda_bf16.h>
#include <math.h>

// Problem constants (fixed by the dataset)
#define BMAX 1024
#define EMAX 32768

// Scratch (static device globals — no allocation allowed)
__device__ long long g_offsets[BMAX + 1];
__device__ int       g_edge_user[EMAX];
__device__ float     g_M2t[64 * 64];      // [j][d] : friend part of Wb^T Wf
__device__ float     g_vself[BMAX * 64];

// ---------------------------------------------------------------------------
// Combo kernel (1024 threads/block, grid = 69):
//   block 0      : dtype-robust scan of counts -> offsets + edge->user map
//   blocks 1..4  : M2t[j][d] = sum_f Wb[f][d] * Wf[f][64+j]   (coalesced)
//   blocks 5..68 : vself[u] = Wb^T (Wf[:, :64] @ self_x[u])   (16 users/block)
// ---------------------------------------------------------------------------
struct VsSmem {
    float Wfh[64][68];   // Wf[:, :64], rows padded
    float Wbt[64][68];   // Wb transposed [d][f], padded
    float sx[16][64];
    float p[16][64];
};
union ComboSmem {
    long long s[BMAX];
    VsSmem vs;
};

__global__ __launch_bounds__(1024)
void combo_kernel(const void* __restrict__ counts_raw, int B, int E,
                  const float* __restrict__ Wf, const float* __restrict__ Wb,
                  const float* __restrict__ self_x) {
    __shared__ ComboSmem sm;
    int b = blockIdx.x;
    int t = threadIdx.x;

    if (b == 0) {
        __shared__ int use64;
        long long* s = sm.s;
        const long long* c64 = (const long long*)counts_raw;
        const int*       c32 = (const int*)counts_raw;

        long long v64 = (t < B) ? c64[t] : 0;
        s[t] = v64;
        __syncthreads();
        for (int o = BMAX >> 1; o > 0; o >>= 1) {
            if (t < o) s[t] += s[t + o];
            __syncthreads();
        }
        if (t == 0) use64 = (s[0] == (long long)E) ? 1 : 0;
        __syncthreads();
        int u64 = use64;
        __syncthreads();

        long long c = 0;
        if (t < B) c = u64 ? c64[t] : (long long)c32[t];
        if (c < 0) c = 0;
        if (c > (long long)EMAX) c = EMAX;

        s[t] = c;
        __syncthreads();
        for (int o = 1; o < BMAX; o <<= 1) {
            long long add = (t >= o) ? s[t - o] : 0;
            __syncthreads();
            s[t] += add;
            __syncthreads();
        }
        if (t == 0) g_offsets[0] = 0;
        if (t < B) g_offsets[t + 1] = s[t];
        long long off = s[t] - c;
        if (t < B) {
            for (long long i = 0; i < c; i++) {
                long long idx = off + i;
                if (idx >= 0 && idx < (long long)EMAX) g_edge_user[idx] = t;
            }
        }
    } else if (b <= 4) {
        int idx = (b - 1) * 1024 + t;
        int d = idx & 63;
        int j = (idx >> 6) & 63;
        float acc = 0.f;
#pragma unroll 8
        for (int f = 0; f < 64; f++)
            acc = fmaf(Wb[f * 64 + d], Wf[f * 128 + 64 + j], acc);
        g_M2t[j * 64 + d] = acc;
    } else {
        VsSmem& S = sm.vs;
        for (int i = t; i < 4096; i += 1024) {
            int f = i >> 6, j = i & 63;
            S.Wfh[f][j] = Wf[f * 128 + j];
        }
        for (int i = t; i < 4096; i += 1024) {
            int f = i >> 6, d = i & 63;
            S.Wbt[d][f] = Wb[i];
        }
        int sub = t >> 6;
        int l = t & 63;
        int u = (b - 5) * 16 + sub;
        S.sx[sub][l] = self_x[u * 64 + l];
        __syncthreads();

        {
            const float4* wr = (const float4*)&S.Wfh[l][0];
            const float4* xr = (const float4*)&S.sx[sub][0];
            float acc = 0.f;
#pragma unroll
            for (int jb = 0; jb < 16; jb++) {
                float4 wv = wr[jb], xv = xr[jb];
                acc = fmaf(wv.x, xv.x, fmaf(wv.y, xv.y,
                      fmaf(wv.z, xv.z, fmaf(wv.w, xv.w, acc))));
            }
            S.p[sub][l] = acc;
        }
        __syncthreads();
        {
            const float4* wr = (const float4*)&S.Wbt[l][0];
            const float4* pr = (const float4*)&S.p[sub][0];
            float acc = 0.f;
#pragma unroll
            for (int fb = 0; fb < 16; fb++) {
                float4 wv = wr[fb], pv = pr[fb];
                acc = fmaf(wv.x, pv.x, fmaf(wv.y, pv.y,
                      fmaf(wv.z, pv.z, fmaf(wv.w, pv.w, acc))));
            }
            g_vself[u * 64 + l] = acc;
        }
    }
}

// ---------------------------------------------------------------------------
// Main (v6): fused v-compute + compacted quad-streaming.
// 8 edges/block (phase B: 1 per warp).
//  Phase A (block-coop): thread owns d=t&63 for edge pair q=t>>6; M2 read
//    once per 2 edges (fx staged interleaved float2) -> crossbar 2x down.
//  Phase B: ballot-compacted row list; lane=r8*8+h8 -> 4 rows/warp-pass,
//    8 lanes/row. 3 shfl + 1 exp + 1 log per 4 rows (vs 16/8 before).
// ---------------------------------------------------------------------------
__global__ __launch_bounds__(256)
void main_kernel(const float* __restrict__ common_x,
                 const float* __restrict__ common_time,
                 const int*   __restrict__ common_src_mask,
                 const float* __restrict__ friend_x,
                 float* __restrict__ out, int max_n, long long out_elems) {
    __shared__ float  M2sh[64 * 64];   // [j][d], 16 KB
    __shared__ float2 fxp[4][64];      // interleaved fx of edge pairs
    __shared__ float  vsh[8][64];
    __shared__ float  exsh[8][64];
    __shared__ int    lst[8][64];

    int tid = threadIdx.x;
    int w = tid >> 5, lane = tid & 31;
    int e = blockIdx.x * 8 + w;

    // ---- stage M2 (block-coop) ----
    {
        const float4* src = (const float4*)g_M2t;
        float4* dst = (float4*)M2sh;
        for (int i = tid; i < 1024; i += 256) dst[i] = src[i];
    }
    // ---- stage interleaved fx pairs ----
    for (int i = tid; i < 256; i += 256) {
        int qq = i >> 6, jj = i & 63;
        int ep = blockIdx.x * 8 + 2 * qq;
        fxp[qq][jj] = make_float2(friend_x[(size_t)ep * 64 + jj],
                                  friend_x[(size_t)(ep + 1) * 64 + jj]);
    }

    // ---- per-warp: masks / temporal / compaction (warp-local only) ----
    const int*   mrow = common_src_mask + (size_t)e * 64;
    const float* trow = common_time + (size_t)e * 64;
    int mk0 = mrow[lane];
    int mk1 = mrow[lane + 32];
    exsh[w][lane]      = __expf(fmaf(trow[lane],      -1e-6f, 1.0f));
    exsh[w][lane + 32] = __expf(fmaf(trow[lane + 32], -1e-6f, 1.0f));
    unsigned bm0 = __ballot_sync(0xffffffffu, mk0 != 0);
    unsigned bm1 = __ballot_sync(0xffffffffu, mk1 != 0);
    int n0 = __popc(bm0);
    if (mk0) lst[w][__popc(bm0 & ((1u << lane) - 1u))] = lane;
    if (mk1) lst[w][n0 + __popc(bm1 & ((1u << lane) - 1u))] = lane + 32;
    int n_act = n0 + __popc(bm1);
    __syncthreads();

    // ---- Phase A: v for edge pair; thread owns one d of edges 2q,2q+1 ----
    {
        int d = tid & 63;
        int q = tid >> 6;
        int eA = blockIdx.x * 8 + 2 * q;
        int uA = g_edge_user[eA], uB = g_edge_user[eA + 1];
        float a0 = g_vself[(size_t)uA * 64 + d];
        float a1 = g_vself[(size_t)uB * 64 + d];
#pragma unroll 8
        for (int j = 0; j < 64; j++) {
            float m = M2sh[j * 64 + d];
            float2 f = fxp[q][j];
            a0 = fmaf(m, f.x, a0);
            a1 = fmaf(m, f.y, a1);
        }
        vsh[2 * q][d]     = a0;
        vsh[2 * q + 1][d] = a1;
    }
    __syncthreads();

    // ---- Phase B: quad-streaming over compacted rows ----
    int h8 = lane & 7, r8 = lane >> 3;
    float4 v4a = *(const float4*)(&vsh[w][h8 * 4]);
    float4 v4b = *(const float4*)(&vsh[w][(h8 + 8) * 4]);
    const float* base = common_x + (size_t)e * 4096;

    float wacc = 0.f;
    int nq = (n_act + 3) >> 2;
#pragma unroll 2
    for (int g2 = 0; g2 < nq; g2++) {
        int i = g2 * 4 + r8;
        bool valid = i < n_act;
        int r = lst[w][valid ? i : 0];
        const float4* rowp = (const float4*)(base + r * 64);
        float4 x1 = rowp[h8];
        float4 x2 = rowp[h8 + 8];
        float p = fmaf(x1.x, v4a.x, fmaf(x1.y, v4a.y,
                  fmaf(x1.z, v4a.z, fmaf(x1.w, v4a.w,
                  fmaf(x2.x, v4b.x, fmaf(x2.y, v4b.y,
                  fmaf(x2.z, v4b.z, x2.w * v4b.w)))))));
        p += __shfl_xor_sync(0xffffffffu, p, 4);
        p += __shfl_xor_sync(0xffffffffu, p, 2);
        p += __shfl_xor_sync(0xffffffffu, p, 1);
        if (valid && h8 == 0) {
            float sp = fmaxf(p, 0.f) + __logf(1.0f + __expf(-fabsf(p)));
            wacc = fmaf(sp, exsh[w][r], wacc);
        }
    }
    // wacc nonzero at lanes 0,8,16,24
    wacc += __shfl_xor_sync(0xffffffffu, wacc, 8);
    wacc += __shfl_xor_sync(0xffffffffu, wacc, 16);
    if (lane == 0) {
        int u = g_edge_user[e];
        long long oi = (long long)u * max_n + (long long)(e - g_offsets[u]);
        if (oi >= 0 && oi < out_elems)
            out[oi] = wacc;
    }
}

// ---------------------------------------------------------------------------
extern "C" void kernel_launch(void* const* d_in, const int* in_sizes, int n_in,
                              void* d_out, int out_size) {
    const float* self_x      = (const float*)d_in[0];
    const float* common_x    = (const float*)d_in[1];
    const float* common_time = (const float*)d_in[2];
    const int*   src_mask    = (const int*)d_in[3];
    const float* friend_x    = (const float*)d_in[4];
    const void*  counts      = (const void*)d_in[5];
    const float* W_friend    = (const float*)d_in[6];
    const float* W_beta      = (const float*)d_in[7];
    float*       out         = (float*)d_out;

    int B = in_sizes[5];
    int E = in_sizes[4] / 64;
    int max_n = out_size / B;

    combo_kernel<<<69, 1024>>>(counts, B, E, W_friend, W_beta, self_x);
    cudaMemsetAsync(d_out, 0, (size_t)out_size * sizeof(float), 0);
    main_kernel<<<E / 8, 256>>>(common_x, common_time, src_mask, friend_x,
                                out, max_n, (long long)out_size);
}

// round 15
// speedup vs baseline: 1.7251x; 1.0244x over previous
#include <cuda_runtime.h>
#include <cuda_bf16.h>
#include <math.h>

// Problem constants (fixed by the dataset)
#define BMAX 1024
#define EMAX 32768

// Scratch (static device globals — no allocation allowed)
__device__ long long g_offsets[BMAX + 1];
__device__ int       g_edge_user[EMAX];
__device__ float     g_M2t[64 * 64];      // [j][d] : friend part of Wb^T Wf
__device__ float     g_vself[BMAX * 64];

// ---------------------------------------------------------------------------
// Combo kernel (1024 threads/block, grid = 69):
//   block 0      : dtype-robust scan of counts -> offsets + edge->user map
//   blocks 1..4  : M2t[j][d] = sum_f Wb[f][d] * Wf[f][64+j]   (coalesced)
//   blocks 5..68 : vself for 16 users/block:
//                    step 1: M1sh[j][d] = sum_f Wb[f][d]*Wf[f][j]  (coalesced
//                            global reads, Wf/Wb L2-resident across blocks)
//                    step 2: vself[u][d] = sum_j M1sh[j][d]*sx[sub][j]
//                            (M1sh lane-consecutive d -> conflict-free;
//                             sx broadcast). No conflicted float4 staging.
// ---------------------------------------------------------------------------
struct VsSmem {
    float M1sh[64 * 64];   // [j][d], 16 KB
    float sx[16][64];      // 4 KB
};
union ComboSmem {
    long long s[BMAX];
    VsSmem vs;
};

__global__ __launch_bounds__(1024)
void combo_kernel(const void* __restrict__ counts_raw, int B, int E,
                  const float* __restrict__ Wf, const float* __restrict__ Wb,
                  const float* __restrict__ self_x) {
    __shared__ ComboSmem sm;
    int b = blockIdx.x;
    int t = threadIdx.x;

    if (b == 0) {
        // ---- setup: scan + edge_user fill ----
        __shared__ int use64;
        long long* s = sm.s;
        const long long* c64 = (const long long*)counts_raw;
        const int*       c32 = (const int*)counts_raw;

        long long v64 = (t < B) ? c64[t] : 0;
        s[t] = v64;
        __syncthreads();
        for (int o = BMAX >> 1; o > 0; o >>= 1) {
            if (t < o) s[t] += s[t + o];
            __syncthreads();
        }
        if (t == 0) use64 = (s[0] == (long long)E) ? 1 : 0;
        __syncthreads();
        int u64 = use64;
        __syncthreads();

        long long c = 0;
        if (t < B) c = u64 ? c64[t] : (long long)c32[t];
        if (c < 0) c = 0;
        if (c > (long long)EMAX) c = EMAX;

        s[t] = c;
        __syncthreads();
        for (int o = 1; o < BMAX; o <<= 1) {
            long long add = (t >= o) ? s[t - o] : 0;
            __syncthreads();
            s[t] += add;
            __syncthreads();
        }
        if (t == 0) g_offsets[0] = 0;
        if (t < B) g_offsets[t + 1] = s[t];
        long long off = s[t] - c;
        if (t < B) {
            for (long long i = 0; i < c; i++) {
                long long idx = off + i;
                if (idx >= 0 && idx < (long long)EMAX) g_edge_user[idx] = t;
            }
        }
    } else if (b <= 4) {
        // ---- M2t (coalesced: d lane-consecutive, j warp-uniform) ----
        int idx = (b - 1) * 1024 + t;          // 0..4095
        int d = idx & 63;
        int j = (idx >> 6) & 63;
        float acc = 0.f;
#pragma unroll 8
        for (int f = 0; f < 64; f++)
            acc = fmaf(Wb[f * 64 + d], Wf[f * 128 + 64 + j], acc);
        g_M2t[j * 64 + d] = acc;
    } else {
        // ---- vself: 16 users/block ----
        VsSmem& S = sm.vs;
        // step 1: M1 into shared, 4 elements per thread, coalesced reads
#pragma unroll
        for (int rep = 0; rep < 4; rep++) {
            int idx = rep * 1024 + t;          // 0..4095
            int d = idx & 63;
            int j = idx >> 6;
            float acc = 0.f;
#pragma unroll 8
            for (int f = 0; f < 64; f++)
                acc = fmaf(Wb[f * 64 + d], Wf[f * 128 + j], acc);
            S.M1sh[j * 64 + d] = acc;
        }
        int sub = t >> 6;          // 0..15 (user within block)
        int d = t & 63;            // 0..63
        int u = (b - 5) * 16 + sub;
        S.sx[sub][d] = (u < B) ? self_x[u * 64 + d] : 0.f;
        __syncthreads();

        // step 2: vself[u][d]  (M1sh conflict-free, sx broadcast)
        float acc = 0.f;
#pragma unroll 16
        for (int j = 0; j < 64; j++)
            acc = fmaf(S.M1sh[j * 64 + d], S.sx[sub][j], acc);
        if (u < B) g_vself[u * 64 + d] = acc;
    }
}

// ---------------------------------------------------------------------------
// Main (v7): fused v-compute + compacted quad-streaming. 8 edges/block.
//  Phase A (block-coop): thread owns d=t&63 for edge pair q=t>>6; M2 read
//    once per 2 edges (fx staged interleaved float2).
//  Phase B: ballot-compacted row list; lane=r8*8+h8 -> 4 rows/warp-pass,
//    8 lanes/row; unroll 4 for MLP. Near the DRAM-page-activation floor.
// ---------------------------------------------------------------------------
__global__ __launch_bounds__(256)
void main_kernel(const float* __restrict__ common_x,
                 const float* __restrict__ common_time,
                 const int*   __restrict__ common_src_mask,
                 const float* __restrict__ friend_x,
                 float* __restrict__ out, int max_n, long long out_elems) {
    __shared__ float  M2sh[64 * 64];   // [j][d], 16 KB
    __shared__ float2 fxp[4][64];      // interleaved fx of edge pairs
    __shared__ float  vsh[8][64];
    __shared__ float  exsh[8][64];
    __shared__ int    lst[8][64];

    int tid = threadIdx.x;
    int w = tid >> 5, lane = tid & 31;
    int e = blockIdx.x * 8 + w;

    // ---- stage M2 (block-coop) ----
    {
        const float4* src = (const float4*)g_M2t;
        float4* dst = (float4*)M2sh;
        for (int i = tid; i < 1024; i += 256) dst[i] = src[i];
    }
    // ---- stage interleaved fx pairs ----
    {
        int qq = tid >> 6, jj = tid & 63;
        int ep = blockIdx.x * 8 + 2 * qq;
        fxp[qq][jj] = make_float2(friend_x[(size_t)ep * 64 + jj],
                                  friend_x[(size_t)(ep + 1) * 64 + jj]);
    }

    // ---- per-warp: masks / temporal / compaction ----
    const int*   mrow = common_src_mask + (size_t)e * 64;
    const float* trow = common_time + (size_t)e * 64;
    int mk0 = mrow[lane];
    int mk1 = mrow[lane + 32];
    exsh[w][lane]      = __expf(fmaf(trow[lane],      -1e-6f, 1.0f));
    exsh[w][lane + 32] = __expf(fmaf(trow[lane + 32], -1e-6f, 1.0f));
    unsigned bm0 = __ballot_sync(0xffffffffu, mk0 != 0);
    unsigned bm1 = __ballot_sync(0xffffffffu, mk1 != 0);
    int n0 = __popc(bm0);
    if (mk0) lst[w][__popc(bm0 & ((1u << lane) - 1u))] = lane;
    if (mk1) lst[w][n0 + __popc(bm1 & ((1u << lane) - 1u))] = lane + 32;
    int n_act = n0 + __popc(bm1);
    __syncthreads();

    // ---- Phase A: v for edge pair; thread owns one d of edges 2q,2q+1 ----
    {
        int d = tid & 63;
        int q = tid >> 6;
        int eA = blockIdx.x * 8 + 2 * q;
        int uA = g_edge_user[eA], uB = g_edge_user[eA + 1];
        float a0 = g_vself[(size_t)uA * 64 + d];
        float a1 = g_vself[(size_t)uB * 64 + d];
#pragma unroll 8
        for (int j = 0; j < 64; j++) {
            float m = M2sh[j * 64 + d];
            float2 f = fxp[q][j];
            a0 = fmaf(m, f.x, a0);
            a1 = fmaf(m, f.y, a1);
        }
        vsh[2 * q][d]     = a0;
        vsh[2 * q + 1][d] = a1;
    }
    __syncthreads();

    // ---- Phase B: quad-streaming over compacted rows ----
    int h8 = lane & 7, r8 = lane >> 3;
    float4 v4a = *(const float4*)(&vsh[w][h8 * 4]);
    float4 v4b = *(const float4*)(&vsh[w][(h8 + 8) * 4]);
    const float* base = common_x + (size_t)e * 4096;

    float wacc = 0.f;
    int nq = (n_act + 3) >> 2;
#pragma unroll 4
    for (int g2 = 0; g2 < nq; g2++) {
        int i = g2 * 4 + r8;
        bool valid = i < n_act;
        int r = lst[w][valid ? i : 0];
        const float4* rowp = (const float4*)(base + r * 64);
        float4 x1 = rowp[h8];
        float4 x2 = rowp[h8 + 8];
        float p = fmaf(x1.x, v4a.x, fmaf(x1.y, v4a.y,
                  fmaf(x1.z, v4a.z, fmaf(x1.w, v4a.w,
                  fmaf(x2.x, v4b.x, fmaf(x2.y, v4b.y,
                  fmaf(x2.z, v4b.z, x2.w * v4b.w)))))));
        p += __shfl_xor_sync(0xffffffffu, p, 4);
        p += __shfl_xor_sync(0xffffffffu, p, 2);
        p += __shfl_xor_sync(0xffffffffu, p, 1);
        if (valid && h8 == 0) {
            float sp = fmaxf(p, 0.f) + __logf(1.0f + __expf(-fabsf(p)));
            wacc = fmaf(sp, exsh[w][r], wacc);
        }
    }
    // wacc nonzero at lanes 0,8,16,24
    wacc += __shfl_xor_sync(0xffffffffu, wacc, 8);
    wacc += __shfl_xor_sync(0xffffffffu, wacc, 16);
    if (lane == 0) {
        int u = g_edge_user[e];
        long long oi = (long long)u * max_n + (long long)(e - g_offsets[u]);
        if (oi >= 0 && oi < out_elems)
            out[oi] = wacc;
    }
}

// ---------------------------------------------------------------------------
extern "C" void kernel_launch(void* const* d_in, const int* in_sizes, int n_in,
                              void* d_out, int out_size) {
    const float* self_x      = (const float*)d_in[0];
    const float* common_x    = (const float*)d_in[1];
    const float* common_time = (const float*)d_in[2];
    const int*   src_mask    = (const int*)d_in[3];
    const float* friend_x    = (const float*)d_in[4];
    const void*  counts      = (const void*)d_in[5];
    const float* W_friend    = (const float*)d_in[6];
    const float* W_beta      = (const float*)d_in[7];
    float*       out         = (float*)d_out;

    int B = in_sizes[5];
    int E = in_sizes[4] / 64;
    int max_n = out_size / B;

    combo_kernel<<<69, 1024>>>(counts, B, E, W_friend, W_beta, self_x);
    cudaMemsetAsync(d_out, 0, (size_t)out_size * sizeof(float), 0);
    main_kernel<<<E / 8, 256>>>(common_x, common_time, src_mask, friend_x,
                                out, max_n, (long long)out_size);
}

// round 16
// speedup vs baseline: 1.7715x; 1.0269x over previous
#include <cuda_runtime.h>
#include <cuda_bf16.h>
#include <math.h>

// Problem constants (fixed by the dataset)
#define BMAX 1024
#define EMAX 32768

// Scratch (static device globals — no allocation allowed)
__device__ long long g_offsets[BMAX + 1];
__device__ int       g_edge_user[EMAX];
__device__ float     g_M2t[64 * 64];      // [j][d] : friend part of Wb^T Wf
__device__ float     g_vself[BMAX * 64];

// ---------------------------------------------------------------------------
// Combo kernel (1024 threads/block, grid = 77):
//   block 0      : dtype-robust scan of counts -> offsets + edge->user map
//   blocks 1..4  : M2t[j][d] = sum_f Wb[f][d] * Wf[f][64+j]   (coalesced)
//   blocks 5..68 : vself for 16 users/block via factorization
//                    P[u][f]    = Wf[f, :64] . sx[u]      (smem, no M1!)
//                    vself[u][d] = sum_f Wb[f][d] * P[u][f]
//                  All LDS conflict-free (stride-65 rows / lane-consec d).
//   blocks 69..76: zero d_out (replaces the separate memset launch)
// ---------------------------------------------------------------------------
struct VsSmem {
    float Wfsh[64][65];   // Wf[:, :64], stride 65 (== 1 mod 32, conflict-free)
    float Wbsh[64 * 64];  // Wb as-is [f][d]
    float Psh[16][65];    // per-user projection
    float sx[16][64];
};
union ComboSmem {
    long long s[BMAX];
    VsSmem vs;
};

__global__ __launch_bounds__(1024)
void combo_kernel(const void* __restrict__ counts_raw, int B, int E,
                  const float* __restrict__ Wf, const float* __restrict__ Wb,
                  const float* __restrict__ self_x,
                  float* __restrict__ outz, long long out_elems) {
    __shared__ ComboSmem sm;
    int b = blockIdx.x;
    int t = threadIdx.x;

    if (b == 0) {
        // ---- setup: scan + edge_user fill ----
        __shared__ int use64;
        long long* s = sm.s;
        const long long* c64 = (const long long*)counts_raw;
        const int*       c32 = (const int*)counts_raw;

        long long v64 = (t < B) ? c64[t] : 0;
        s[t] = v64;
        __syncthreads();
        for (int o = BMAX >> 1; o > 0; o >>= 1) {
            if (t < o) s[t] += s[t + o];
            __syncthreads();
        }
        if (t == 0) use64 = (s[0] == (long long)E) ? 1 : 0;
        __syncthreads();
        int u64 = use64;
        __syncthreads();

        long long c = 0;
        if (t < B) c = u64 ? c64[t] : (long long)c32[t];
        if (c < 0) c = 0;
        if (c > (long long)EMAX) c = EMAX;

        s[t] = c;
        __syncthreads();
        for (int o = 1; o < BMAX; o <<= 1) {
            long long add = (t >= o) ? s[t - o] : 0;
            __syncthreads();
            s[t] += add;
            __syncthreads();
        }
        if (t == 0) g_offsets[0] = 0;
        if (t < B) g_offsets[t + 1] = s[t];
        long long off = s[t] - c;
        if (t < B) {
            for (long long i = 0; i < c; i++) {
                long long idx = off + i;
                if (idx >= 0 && idx < (long long)EMAX) g_edge_user[idx] = t;
            }
        }
    } else if (b <= 4) {
        // ---- M2t (coalesced: d lane-consecutive, j warp-uniform) ----
        int idx = (b - 1) * 1024 + t;          // 0..4095
        int d = idx & 63;
        int j = (idx >> 6) & 63;
        float acc = 0.f;
#pragma unroll 8
        for (int f = 0; f < 64; f++)
            acc = fmaf(Wb[f * 64 + d], Wf[f * 128 + 64 + j], acc);
        g_M2t[j * 64 + d] = acc;
    } else if (b <= 68) {
        // ---- vself: 16 users/block, factorized, no M1 recompute ----
        VsSmem& S = sm.vs;
        for (int i = t; i < 4096; i += 1024) {
            int f = i >> 6, j = i & 63;
            S.Wfsh[f][j] = Wf[f * 128 + j];    // coalesced 64-float rows
        }
        for (int i = t; i < 4096; i += 1024) {
            S.Wbsh[i] = Wb[i];                 // fully coalesced
        }
        int sub = t >> 6;          // 0..15 (user within block)
        int l = t & 63;            // f in step 1, d in step 2
        int u = (b - 5) * 16 + sub;
        S.sx[sub][l] = (u < B) ? self_x[u * 64 + l] : 0.f;
        __syncthreads();

        // step 1: P[sub][f] = Wf[f, :64] . sx[sub]
        {
            float acc = 0.f;
#pragma unroll 16
            for (int j = 0; j < 64; j++)
                acc = fmaf(S.Wfsh[l][j], S.sx[sub][j], acc);  // stride-65 + bcast
            S.Psh[sub][l] = acc;
        }
        __syncthreads();
        // step 2: vself[u][d] = sum_f Wb[f][d] * P[sub][f]
        {
            float acc = 0.f;
#pragma unroll 16
            for (int f = 0; f < 64; f++)
                acc = fmaf(S.Wbsh[f * 64 + l], S.Psh[sub][f], acc);
            if (u < B) g_vself[u * 64 + l] = acc;
        }
    } else {
        // ---- zero the output buffer (padding must be 0) ----
        long long base = (long long)(b - 69) * 1024 + t;
        for (long long i = base; i < out_elems; i += 8LL * 1024)
            outz[i] = 0.f;
    }
}

// ---------------------------------------------------------------------------
// Main (v7, at its DRAM-activation floor): fused v-compute + compacted
// quad-streaming. 8 edges/block.
// ---------------------------------------------------------------------------
__global__ __launch_bounds__(256)
void main_kernel(const float* __restrict__ common_x,
                 const float* __restrict__ common_time,
                 const int*   __restrict__ common_src_mask,
                 const float* __restrict__ friend_x,
                 float* __restrict__ out, int max_n, long long out_elems) {
    __shared__ float  M2sh[64 * 64];   // [j][d], 16 KB
    __shared__ float2 fxp[4][64];      // interleaved fx of edge pairs
    __shared__ float  vsh[8][64];
    __shared__ float  exsh[8][64];
    __shared__ int    lst[8][64];

    int tid = threadIdx.x;
    int w = tid >> 5, lane = tid & 31;
    int e = blockIdx.x * 8 + w;

    // ---- stage M2 (block-coop) ----
    {
        const float4* src = (const float4*)g_M2t;
        float4* dst = (float4*)M2sh;
        for (int i = tid; i < 1024; i += 256) dst[i] = src[i];
    }
    // ---- stage interleaved fx pairs ----
    {
        int qq = tid >> 6, jj = tid & 63;
        int ep = blockIdx.x * 8 + 2 * qq;
        fxp[qq][jj] = make_float2(friend_x[(size_t)ep * 64 + jj],
                                  friend_x[(size_t)(ep + 1) * 64 + jj]);
    }

    // ---- per-warp: masks / temporal / compaction ----
    const int*   mrow = common_src_mask + (size_t)e * 64;
    const float* trow = common_time + (size_t)e * 64;
    int mk0 = mrow[lane];
    int mk1 = mrow[lane + 32];
    exsh[w][lane]      = __expf(fmaf(trow[lane],      -1e-6f, 1.0f));
    exsh[w][lane + 32] = __expf(fmaf(trow[lane + 32], -1e-6f, 1.0f));
    unsigned bm0 = __ballot_sync(0xffffffffu, mk0 != 0);
    unsigned bm1 = __ballot_sync(0xffffffffu, mk1 != 0);
    int n0 = __popc(bm0);
    if (mk0) lst[w][__popc(bm0 & ((1u << lane) - 1u))] = lane;
    if (mk1) lst[w][n0 + __popc(bm1 & ((1u << lane) - 1u))] = lane + 32;
    int n_act = n0 + __popc(bm1);
    __syncthreads();

    // ---- Phase A: v for edge pair; thread owns one d of edges 2q,2q+1 ----
    {
        int d = tid & 63;
        int q = tid >> 6;
        int eA = blockIdx.x * 8 + 2 * q;
        int uA = g_edge_user[eA], uB = g_edge_user[eA + 1];
        float a0 = g_vself[(size_t)uA * 64 + d];
        float a1 = g_vself[(size_t)uB * 64 + d];
#pragma unroll 8
        for (int j = 0; j < 64; j++) {
            float m = M2sh[j * 64 + d];
            float2 f = fxp[q][j];
            a0 = fmaf(m, f.x, a0);
            a1 = fmaf(m, f.y, a1);
        }
        vsh[2 * q][d]     = a0;
        vsh[2 * q + 1][d] = a1;
    }
    __syncthreads();

    // ---- Phase B: quad-streaming over compacted rows ----
    int h8 = lane & 7, r8 = lane >> 3;
    float4 v4a = *(const float4*)(&vsh[w][h8 * 4]);
    float4 v4b = *(const float4*)(&vsh[w][(h8 + 8) * 4]);
    const float* base = common_x + (size_t)e * 4096;

    float wacc = 0.f;
    int nq = (n_act + 3) >> 2;
#pragma unroll 4
    for (int g2 = 0; g2 < nq; g2++) {
        int i = g2 * 4 + r8;
        bool valid = i < n_act;
        int r = lst[w][valid ? i : 0];
        const float4* rowp = (const float4*)(base + r * 64);
        float4 x1 = rowp[h8];
        float4 x2 = rowp[h8 + 8];
        float p = fmaf(x1.x, v4a.x, fmaf(x1.y, v4a.y,
                  fmaf(x1.z, v4a.z, fmaf(x1.w, v4a.w,
                  fmaf(x2.x, v4b.x, fmaf(x2.y, v4b.y,
                  fmaf(x2.z, v4b.z, x2.w * v4b.w)))))));
        p += __shfl_xor_sync(0xffffffffu, p, 4);
        p += __shfl_xor_sync(0xffffffffu, p, 2);
        p += __shfl_xor_sync(0xffffffffu, p, 1);
        if (valid && h8 == 0) {
            float sp = fmaxf(p, 0.f) + __logf(1.0f + __expf(-fabsf(p)));
            wacc = fmaf(sp, exsh[w][r], wacc);
        }
    }
    // wacc nonzero at lanes 0,8,16,24
    wacc += __shfl_xor_sync(0xffffffffu, wacc, 8);
    wacc += __shfl_xor_sync(0xffffffffu, wacc, 16);
    if (lane == 0) {
        int u = g_edge_user[e];
        long long oi = (long long)u * max_n + (long long)(e - g_offsets[u]);
        if (oi >= 0 && oi < out_elems)
            out[oi] = wacc;
    }
}

// ---------------------------------------------------------------------------
extern "C" void kernel_launch(void* const* d_in, const int* in_sizes, int n_in,
                              void* d_out, int out_size) {
    const float* self_x      = (const float*)d_in[0];
    const float* common_x    = (const float*)d_in[1];
    const float* common_time = (const float*)d_in[2];
    const int*   src_mask    = (const int*)d_in[3];
    const float* friend_x    = (const float*)d_in[4];
    const void*  counts      = (const void*)d_in[5];
    const float* W_friend    = (const float*)d_in[6];
    const float* W_beta      = (const float*)d_in[7];
    float*       out         = (float*)d_out;

    int B = in_sizes[5];
    int E = in_sizes[4] / 64;
    int max_n = out_size / B;

    combo_kernel<<<77, 1024>>>(counts, B, E, W_friend, W_beta, self_x,
                               out, (long long)out_size);
    main_kernel<<<E / 8, 256>>>(common_x, common_time, src_mask, friend_x,
                                out, max_n, (long long)out_size);
}